// round 1
// baseline (speedup 1.0000x reference)
#include <cuda_runtime.h>
#include <math.h>

#define NT    4096   // trajectories
#define SEQ   128    // L
#define DIN   32     // input_dim
#define DLAT  64     // latent_dim
#define NU    256    // n_units
#define INDIM 160    // 2*DLAT + DIN
#define TM    32     // trajectories per CTA
#define NTH   256    // threads per CTA

struct SmemLayout {
    float y[TM * DLAT];        // current mean state
    float lv[TM * DLAT];       // current logvar state
    float yc[TM * INDIM];      // [yi_ode, lv, x]
    float cc[TM * INDIM];      // [yi_ode*r, lv*r, x]
    float h1[TM * NU];         // hidden layer buffer
    float u[TM * DLAT];        // update gate
    float rg[TM * DLAT];       // reset gate
    float hh[TM * 2 * DLAT];   // candidate output (128 wide)
    float tmp[TM * DLAT];      // ODE mlp output
    float ts[SEQ];             // time steps
};

__device__ __forceinline__ float sigmoid_f(float x) {
    return 1.0f / (1.0f + expf(-x));
}

// O[TM][N] = act(A[TM][K] @ W[K][N] + b[N])
// ACT: 0 = none, 1 = tanh, 2 = sigmoid
template<int K, int N, int ACT>
__device__ __forceinline__ void gemm_tile(const float* __restrict__ A,   // smem
                                          const float* __restrict__ W,   // gmem, row-major KxN
                                          const float* __restrict__ bias,// gmem, N
                                          float* __restrict__ O,         // smem
                                          int tid)
{
    constexpr int NCG = N / 4;          // column groups (float4)
    constexpr int RG  = NTH / NCG;      // row groups
    constexpr int RPT = TM / RG;        // rows per thread
    const int cg = tid % NCG;
    const int rg = tid / NCG;

    float acc[RPT][4];
#pragma unroll
    for (int r = 0; r < RPT; ++r) {
        acc[r][0] = 0.f; acc[r][1] = 0.f; acc[r][2] = 0.f; acc[r][3] = 0.f;
    }

    const float*  Ab = A + rg * RPT * K;
    const float4* Wb = reinterpret_cast<const float4*>(W) + cg;

#pragma unroll 4
    for (int k = 0; k < K; ++k) {
        float4 w = Wb[k * (N / 4)];
#pragma unroll
        for (int r = 0; r < RPT; ++r) {
            float a = Ab[r * K + k];
            acc[r][0] = fmaf(a, w.x, acc[r][0]);
            acc[r][1] = fmaf(a, w.y, acc[r][1]);
            acc[r][2] = fmaf(a, w.z, acc[r][2]);
            acc[r][3] = fmaf(a, w.w, acc[r][3]);
        }
    }

    float4 b4 = reinterpret_cast<const float4*>(bias)[cg];
#pragma unroll
    for (int r = 0; r < RPT; ++r) {
        float4 o;
        o.x = acc[r][0] + b4.x;
        o.y = acc[r][1] + b4.y;
        o.z = acc[r][2] + b4.z;
        o.w = acc[r][3] + b4.w;
        if (ACT == 1) {
            o.x = tanhf(o.x); o.y = tanhf(o.y); o.z = tanhf(o.z); o.w = tanhf(o.w);
        } else if (ACT == 2) {
            o.x = sigmoid_f(o.x); o.y = sigmoid_f(o.y);
            o.z = sigmoid_f(o.z); o.w = sigmoid_f(o.w);
        }
        reinterpret_cast<float4*>(O + (rg * RPT + r) * N)[cg] = o;
    }
}

__global__ __launch_bounds__(NTH, 1)
void ode_rnn_kernel(const float* __restrict__ data,
                    const float* __restrict__ tsteps,
                    const float* __restrict__ Wo1, const float* __restrict__ bo1,
                    const float* __restrict__ Wo2, const float* __restrict__ bo2,
                    const float* __restrict__ Wu1, const float* __restrict__ bu1,
                    const float* __restrict__ Wu2, const float* __restrict__ bu2,
                    const float* __restrict__ Wr1, const float* __restrict__ br1,
                    const float* __restrict__ Wr2, const float* __restrict__ br2,
                    const float* __restrict__ Wn1, const float* __restrict__ bn1,
                    const float* __restrict__ Wn2, const float* __restrict__ bn2,
                    float* __restrict__ out)
{
    extern __shared__ float smem_raw[];
    SmemLayout* S = reinterpret_cast<SmemLayout*>(smem_raw);
    const int tid = threadIdx.x;
    const int traj0 = blockIdx.x * TM;

    // init state to zero, stage time steps
    for (int i = tid; i < TM * DLAT; i += NTH) { S->y[i] = 0.f; S->lv[i] = 0.f; }
    for (int i = tid; i < SEQ; i += NTH) S->ts[i] = tsteps[i];
    __syncthreads();

    for (int s = 0; s < SEQ - 1; ++s) {
        // dts = concat([ts[1]-ts[0], ts[1:-1]-ts[2:]])
        const float dt = (s == 0) ? (S->ts[1] - S->ts[0]) : (S->ts[s] - S->ts[s + 1]);

        // stage x -> yc[:,128:160], lv -> yc[:,64:128]
        for (int i = tid; i < TM * DIN; i += NTH) {
            int r = i / DIN, c = i % DIN;
            S->yc[r * INDIM + 2 * DLAT + c] =
                data[(size_t)(traj0 + r) * SEQ * DIN + (size_t)(s + 1) * DIN + c];
        }
        for (int i = tid; i < TM * DLAT; i += NTH) {
            int r = i / DLAT, c = i % DLAT;
            S->yc[r * INDIM + DLAT + c] = S->lv[i];
        }
        // (no sync needed: next gemm reads S->y, which is stable; sync after gemm covers yc)

        // ODE MLP: tmp = tanh(y@Wo1+bo1)@Wo2+bo2
        gemm_tile<DLAT, NU, 1>(S->y, Wo1, bo1, S->h1, tid);
        __syncthreads();
        gemm_tile<NU, DLAT, 0>(S->h1, Wo2, bo2, S->tmp, tid);
        __syncthreads();
        // yi_ode = y + tmp*dt -> yc[:,0:64]
        for (int i = tid; i < TM * DLAT; i += NTH) {
            int r = i / DLAT, c = i % DLAT;
            S->yc[r * INDIM + c] = S->y[i] + S->tmp[i] * dt;
        }
        __syncthreads();

        // update gate
        gemm_tile<INDIM, NU, 1>(S->yc, Wu1, bu1, S->h1, tid);
        __syncthreads();
        gemm_tile<NU, DLAT, 2>(S->h1, Wu2, bu2, S->u, tid);
        __syncthreads();

        // reset gate
        gemm_tile<INDIM, NU, 1>(S->yc, Wr1, br1, S->h1, tid);
        __syncthreads();
        gemm_tile<NU, DLAT, 2>(S->h1, Wr2, br2, S->rg, tid);
        __syncthreads();

        // cc = yc * [reset, reset, 1]
        for (int i = tid; i < TM * INDIM; i += NTH) {
            int r = i / INDIM, c = i % INDIM;
            float v = S->yc[i];
            if (c < 2 * DLAT) v *= S->rg[r * DLAT + (c & (DLAT - 1))];
            S->cc[i] = v;
        }
        __syncthreads();

        // candidate: hh = tanh(cc@Wn1+bn1)@Wn2+bn2  (N=128)
        gemm_tile<INDIM, NU, 1>(S->cc, Wn1, bn1, S->h1, tid);
        __syncthreads();
        gemm_tile<NU, 2 * DLAT, 0>(S->h1, Wn2, bn2, S->hh, tid);
        __syncthreads();

        // state update
        for (int i = tid; i < TM * DLAT; i += NTH) {
            int r = i / DLAT, c = i % DLAT;
            float uu   = S->u[i];
            float ns   = S->hh[r * 2 * DLAT + c];
            float nstd = fabsf(S->hh[r * 2 * DLAT + DLAT + c]);
            S->y[i]  = (1.f - uu) * ns   + uu * S->yc[r * INDIM + c];
            S->lv[i] = (1.f - uu) * nstd + uu * S->lv[i];
        }
        __syncthreads();
    }

    // output: yi (4096x64) then yi_logvar (4096x64)
    for (int i = tid; i < TM * DLAT; i += NTH) {
        int r = i / DLAT, c = i % DLAT;
        out[(size_t)(traj0 + r) * DLAT + c] = S->y[i];
        out[(size_t)NT * DLAT + (size_t)(traj0 + r) * DLAT + c] = S->lv[i];
    }
}

extern "C" void kernel_launch(void* const* d_in, const int* in_sizes, int n_in,
                              void* d_out, int out_size) {
    const float* data = (const float*)d_in[0];
    const float* ts   = (const float*)d_in[1];
    const float* Wo1  = (const float*)d_in[2];
    const float* bo1  = (const float*)d_in[3];
    const float* Wo2  = (const float*)d_in[4];
    const float* bo2  = (const float*)d_in[5];
    const float* Wu1  = (const float*)d_in[6];
    const float* bu1  = (const float*)d_in[7];
    const float* Wu2  = (const float*)d_in[8];
    const float* bu2  = (const float*)d_in[9];
    const float* Wr1  = (const float*)d_in[10];
    const float* br1  = (const float*)d_in[11];
    const float* Wr2  = (const float*)d_in[12];
    const float* br2  = (const float*)d_in[13];
    const float* Wn1  = (const float*)d_in[14];
    const float* bn1  = (const float*)d_in[15];
    const float* Wn2  = (const float*)d_in[16];
    const float* bn2  = (const float*)d_in[17];
    float* out = (float*)d_out;

    const int smem = (int)sizeof(SmemLayout);
    cudaFuncSetAttribute(ode_rnn_kernel,
                         cudaFuncAttributeMaxDynamicSharedMemorySize, smem);
    ode_rnn_kernel<<<NT / TM, NTH, smem>>>(
        data, ts, Wo1, bo1, Wo2, bo2, Wu1, bu1, Wu2, bu2,
        Wr1, br1, Wr2, br2, Wn1, bn1, Wn2, bn2, out);
}

// round 2
// speedup vs baseline: 1.4688x; 1.4688x over previous
#include <cuda_runtime.h>
#include <math.h>

#define NT    4096   // trajectories
#define SEQ   128    // L
#define DIN   32     // input_dim
#define DLAT  64     // latent_dim
#define NU    256    // n_units
#define INDIM 160    // 2*DLAT + DIN
#define TM    32     // trajectories per CTA
#define NTH   256    // threads per CTA
#define TS    34     // padded stride for transposed smem buffers (even, +2 pad)

typedef unsigned long long u64;

// ---------- packed f32x2 helpers ----------
__device__ __forceinline__ u64 bcast2(float a) {
    u64 r; asm("mov.b64 %0, {%1, %1};" : "=l"(r) : "f"(a)); return r;
}
__device__ __forceinline__ u64 pk2(float x, float y) {
    u64 r; asm("mov.b64 %0, {%1, %2};" : "=l"(r) : "f"(x), "f"(y)); return r;
}
__device__ __forceinline__ float2 unpk(u64 v) {
    float2 f; asm("mov.b64 {%0, %1}, %2;" : "=f"(f.x), "=f"(f.y) : "l"(v)); return f;
}
__device__ __forceinline__ void fma2(u64& d, u64 a, u64 b) {
    asm("fma.rn.f32x2 %0, %1, %2, %0;" : "+l"(d) : "l"(a), "l"(b));
}
__device__ __forceinline__ u64 mul2(u64 a, u64 b) {
    u64 d; asm("mul.rn.f32x2 %0, %1, %2;" : "=l"(d) : "l"(a), "l"(b)); return d;
}

__device__ __forceinline__ float sigmoid_f(float x) {
    return 1.0f / (1.0f + expf(-x));
}

struct SmemLayout {
    float yT[DLAT * TS];    // mean state, transposed  [c][r]
    float lvT[DLAT * TS];   // logvar state, transposed
    float ycT[INDIM * TS];  // [yi_ode ; lv ; x], transposed
    float ccT[INDIM * TS];  // [yi_ode*r ; lv*r ; x], transposed
    float h1T[NU * TS];     // hidden activations, transposed
    float u[TM * DLAT];     // update gate, row-major
    float ts[SEQ];
};

// ---------- GEMM 1st layers: h1T = tanh(AT^T @ W + b), N=256, transposed out ----------
// AT: smem [K][TS]; W: gmem [K][256]; out h1T: smem [256][TS]
template<int K>
__device__ __forceinline__ void gemm_h1(const float* __restrict__ AT,
                                        const float* __restrict__ W,
                                        const float* __restrict__ bias,
                                        float* __restrict__ OT, int tid)
{
    constexpr int NCG = NU / 4;   // 64 col groups
    constexpr int RG  = NTH / NCG; // 4
    constexpr int RPT = TM / RG;   // 8 rows
    constexpr int PR  = RPT / 2;   // 4 row-pairs
    const int cg = tid % NCG;
    const int r0 = (tid / NCG) * RPT;

    u64 acc[PR][4];
#pragma unroll
    for (int p = 0; p < PR; ++p) { acc[p][0]=0; acc[p][1]=0; acc[p][2]=0; acc[p][3]=0; }

    const float4* W4 = reinterpret_cast<const float4*>(W) + cg;
#pragma unroll 8
    for (int k = 0; k < K; ++k) {
        float4 w = W4[k * (NU / 4)];
        u64 w0 = bcast2(w.x), w1 = bcast2(w.y), w2 = bcast2(w.z), w3 = bcast2(w.w);
        const u64* ap = reinterpret_cast<const u64*>(AT + k * TS + r0);
#pragma unroll
        for (int p = 0; p < PR; ++p) {
            u64 a2 = ap[p];
            fma2(acc[p][0], a2, w0);
            fma2(acc[p][1], a2, w1);
            fma2(acc[p][2], a2, w2);
            fma2(acc[p][3], a2, w3);
        }
    }
    float4 b4 = reinterpret_cast<const float4*>(bias)[cg];
    float bb[4] = {b4.x, b4.y, b4.z, b4.w};
#pragma unroll
    for (int p = 0; p < PR; ++p) {
#pragma unroll
        for (int j = 0; j < 4; ++j) {
            float2 v = unpk(acc[p][j]);
            v.x = tanhf(v.x + bb[j]);
            v.y = tanhf(v.y + bb[j]);
            *reinterpret_cast<u64*>(OT + (4 * cg + j) * TS + r0 + 2 * p) = pk2(v.x, v.y);
        }
    }
}

// ---------- generic N=64 second-layer accumulate (K=256) ----------
// returns acc pairs (rows r0,r0+1) for cols 4cg..4cg+3 ; caller applies epilogue
__device__ __forceinline__ void gemm64_acc(const float* __restrict__ AT,
                                           const float* __restrict__ W,
                                           u64 acc[4], int cg, int r0)
{
    acc[0] = 0; acc[1] = 0; acc[2] = 0; acc[3] = 0;
    const float4* W4 = reinterpret_cast<const float4*>(W) + cg;
#pragma unroll 8
    for (int k = 0; k < NU; ++k) {
        float4 w = W4[k * (DLAT / 4)];
        u64 a2 = *reinterpret_cast<const u64*>(AT + k * TS + r0);
        fma2(acc[0], a2, bcast2(w.x));
        fma2(acc[1], a2, bcast2(w.y));
        fma2(acc[2], a2, bcast2(w.z));
        fma2(acc[3], a2, bcast2(w.w));
    }
}

__global__ __launch_bounds__(NTH, 1)
void ode_rnn_kernel(const float* __restrict__ data,
                    const float* __restrict__ tsteps,
                    const float* __restrict__ Wo1, const float* __restrict__ bo1,
                    const float* __restrict__ Wo2, const float* __restrict__ bo2,
                    const float* __restrict__ Wu1, const float* __restrict__ bu1,
                    const float* __restrict__ Wu2, const float* __restrict__ bu2,
                    const float* __restrict__ Wr1, const float* __restrict__ br1,
                    const float* __restrict__ Wr2, const float* __restrict__ br2,
                    const float* __restrict__ Wn1, const float* __restrict__ bn1,
                    const float* __restrict__ Wn2, const float* __restrict__ bn2,
                    float* __restrict__ out)
{
    extern __shared__ float smem_raw[];
    SmemLayout* S = reinterpret_cast<SmemLayout*>(smem_raw);
    const int tid = threadIdx.x;
    const int traj0 = blockIdx.x * TM;

    // zero state, stage time steps
    for (int i = tid; i < DLAT * TS; i += NTH) { S->yT[i] = 0.f; S->lvT[i] = 0.f; }
    for (int i = tid; i < SEQ; i += NTH) S->ts[i] = tsteps[i];
    __syncthreads();

    // per-thread geometry for N=64 stages
    const int cg64 = tid % 16;        // 16 col groups of 4
    const int r064 = (tid / 16) * 2;  // row pair base

    for (int s = 0; s < SEQ - 1; ++s) {
        const float dt = (s == 0) ? (S->ts[1] - S->ts[0]) : (S->ts[s] - S->ts[s + 1]);

        // ---- stage lv -> ycT[64:128], x -> ycT[128:160] & ccT[128:160] ----
        for (int i = tid; i < DLAT * (TM / 2); i += NTH) {
            int c = i / (TM / 2), p = i % (TM / 2);
            u64 v = *reinterpret_cast<const u64*>(S->lvT + c * TS + 2 * p);
            *reinterpret_cast<u64*>(S->ycT + (DLAT + c) * TS + 2 * p) = v;
        }
        for (int i = tid; i < DIN * TM; i += NTH) {
            int c = i % DIN, r = i / DIN;
            float v = data[(size_t)(traj0 + r) * SEQ * DIN + (size_t)(s + 1) * DIN + c];
            S->ycT[(2 * DLAT + c) * TS + r] = v;
            S->ccT[(2 * DLAT + c) * TS + r] = v;
        }

        // ---- ODE MLP layer 1 ----
        gemm_h1<DLAT>(S->yT, Wo1, bo1, S->h1T, tid);
        __syncthreads();

        // ---- ODE MLP layer 2, epilogue: ycT[0:64] = y + o*dt ----
        {
            u64 acc[4];
            gemm64_acc(S->h1T, Wo2, acc, cg64, r064);
            float4 b4 = reinterpret_cast<const float4*>(bo2)[cg64];
            float bb[4] = {b4.x, b4.y, b4.z, b4.w};
#pragma unroll
            for (int j = 0; j < 4; ++j) {
                int c = 4 * cg64 + j;
                float2 o = unpk(acc[j]);
                float2 y = unpk(*reinterpret_cast<const u64*>(S->yT + c * TS + r064));
                float2 r;
                r.x = fmaf(o.x + bb[j], dt, y.x);
                r.y = fmaf(o.y + bb[j], dt, y.y);
                *reinterpret_cast<u64*>(S->ycT + c * TS + r064) = pk2(r.x, r.y);
            }
        }
        __syncthreads();

        // ---- update gate ----
        gemm_h1<INDIM>(S->ycT, Wu1, bu1, S->h1T, tid);
        __syncthreads();
        {
            u64 acc[4];
            gemm64_acc(S->h1T, Wu2, acc, cg64, r064);
            float4 b4 = reinterpret_cast<const float4*>(bu2)[cg64];
            float bb[4] = {b4.x, b4.y, b4.z, b4.w};
            float4 o0, o1;
            float* p0 = &o0.x; float* p1 = &o1.x;
#pragma unroll
            for (int j = 0; j < 4; ++j) {
                float2 v = unpk(acc[j]);
                p0[j] = sigmoid_f(v.x + bb[j]);
                p1[j] = sigmoid_f(v.y + bb[j]);
            }
            reinterpret_cast<float4*>(S->u + r064 * DLAT)[cg64] = o0;
            reinterpret_cast<float4*>(S->u + (r064 + 1) * DLAT)[cg64] = o1;
        }
        __syncthreads();

        // ---- reset gate, epilogue builds ccT[0:128] ----
        gemm_h1<INDIM>(S->ycT, Wr1, br1, S->h1T, tid);
        __syncthreads();
        {
            u64 acc[4];
            gemm64_acc(S->h1T, Wr2, acc, cg64, r064);
            float4 b4 = reinterpret_cast<const float4*>(br2)[cg64];
            float bb[4] = {b4.x, b4.y, b4.z, b4.w};
#pragma unroll
            for (int j = 0; j < 4; ++j) {
                int c = 4 * cg64 + j;
                float2 v = unpk(acc[j]);
                u64 rp = pk2(sigmoid_f(v.x + bb[j]), sigmoid_f(v.y + bb[j]));
                u64 ylo = *reinterpret_cast<const u64*>(S->ycT + c * TS + r064);
                u64 yhi = *reinterpret_cast<const u64*>(S->ycT + (c + DLAT) * TS + r064);
                *reinterpret_cast<u64*>(S->ccT + c * TS + r064) = mul2(ylo, rp);
                *reinterpret_cast<u64*>(S->ccT + (c + DLAT) * TS + r064) = mul2(yhi, rp);
            }
        }
        __syncthreads();

        // ---- candidate MLP layer 1 ----
        gemm_h1<INDIM>(S->ccT, Wn1, bn1, S->h1T, tid);
        __syncthreads();

        // ---- candidate layer 2 (N=128) + fused state update ----
        {
            u64 accA[4], accB[4];  // cols c..c+3 (new_state) and c+64..c+67 (new_std)
#pragma unroll
            for (int j = 0; j < 4; ++j) { accA[j] = 0; accB[j] = 0; }
            const float4* W4 = reinterpret_cast<const float4*>(Wn2);
#pragma unroll 8
            for (int k = 0; k < NU; ++k) {
                float4 wl = W4[k * (2 * DLAT / 4) + cg64];
                float4 wh = W4[k * (2 * DLAT / 4) + cg64 + 16];
                u64 a2 = *reinterpret_cast<const u64*>(S->h1T + k * TS + r064);
                fma2(accA[0], a2, bcast2(wl.x));
                fma2(accA[1], a2, bcast2(wl.y));
                fma2(accA[2], a2, bcast2(wl.z));
                fma2(accA[3], a2, bcast2(wl.w));
                fma2(accB[0], a2, bcast2(wh.x));
                fma2(accB[1], a2, bcast2(wh.y));
                fma2(accB[2], a2, bcast2(wh.z));
                fma2(accB[3], a2, bcast2(wh.w));
            }
            float4 bl = reinterpret_cast<const float4*>(bn2)[cg64];
            float4 bh = reinterpret_cast<const float4*>(bn2)[cg64 + 16];
            float bbl[4] = {bl.x, bl.y, bl.z, bl.w};
            float bbh[4] = {bh.x, bh.y, bh.z, bh.w};
#pragma unroll
            for (int j = 0; j < 4; ++j) {
                int c = 4 * cg64 + j;
                float2 ns = unpk(accA[j]);
                ns.x += bbl[j]; ns.y += bbl[j];
                float2 nd = unpk(accB[j]);
                nd.x = fabsf(nd.x + bbh[j]); nd.y = fabsf(nd.y + bbh[j]);
                float u0 = S->u[r064 * DLAT + c];
                float u1 = S->u[(r064 + 1) * DLAT + c];
                float2 yo = unpk(*reinterpret_cast<const u64*>(S->ycT + c * TS + r064));
                float2 lo = unpk(*reinterpret_cast<const u64*>(S->lvT + c * TS + r064));
                float ny0 = (1.f - u0) * ns.x + u0 * yo.x;
                float ny1 = (1.f - u1) * ns.y + u1 * yo.y;
                float nl0 = (1.f - u0) * nd.x + u0 * lo.x;
                float nl1 = (1.f - u1) * nd.y + u1 * lo.y;
                *reinterpret_cast<u64*>(S->yT + c * TS + r064)  = pk2(ny0, ny1);
                *reinterpret_cast<u64*>(S->lvT + c * TS + r064) = pk2(nl0, nl1);
            }
        }
        __syncthreads();
    }

    // ---- output: yi (4096x64) then yi_logvar (4096x64) ----
    for (int i = tid; i < TM * DLAT; i += NTH) {
        int c = i % DLAT, r = i / DLAT;
        out[(size_t)(traj0 + r) * DLAT + c] = S->yT[c * TS + r];
        out[(size_t)NT * DLAT + (size_t)(traj0 + r) * DLAT + c] = S->lvT[c * TS + r];
    }
}

extern "C" void kernel_launch(void* const* d_in, const int* in_sizes, int n_in,
                              void* d_out, int out_size) {
    const float* data = (const float*)d_in[0];
    const float* ts   = (const float*)d_in[1];
    const float* Wo1  = (const float*)d_in[2];
    const float* bo1  = (const float*)d_in[3];
    const float* Wo2  = (const float*)d_in[4];
    const float* bo2  = (const float*)d_in[5];
    const float* Wu1  = (const float*)d_in[6];
    const float* bu1  = (const float*)d_in[7];
    const float* Wu2  = (const float*)d_in[8];
    const float* bu2  = (const float*)d_in[9];
    const float* Wr1  = (const float*)d_in[10];
    const float* br1  = (const float*)d_in[11];
    const float* Wr2  = (const float*)d_in[12];
    const float* br2  = (const float*)d_in[13];
    const float* Wn1  = (const float*)d_in[14];
    const float* bn1  = (const float*)d_in[15];
    const float* Wn2  = (const float*)d_in[16];
    const float* bn2  = (const float*)d_in[17];
    float* out = (float*)d_out;

    const int smem = (int)sizeof(SmemLayout);
    cudaFuncSetAttribute(ode_rnn_kernel,
                         cudaFuncAttributeMaxDynamicSharedMemorySize, smem);
    ode_rnn_kernel<<<NT / TM, NTH, smem>>>(
        data, ts, Wo1, bo1, Wo2, bo2, Wu1, bu1, Wu2, bu2,
        Wr1, br1, Wr2, br2, Wn1, bn1, Wn2, bn2, out);
}